// round 7
// baseline (speedup 1.0000x reference)
#include <cuda_runtime.h>
#include <cuda_bf16.h>
#include <math.h>
#include <stdint.h>

#define TT   2048
#define DD   1024
#define NH   16
#define HDIM 64
#define WIN  128
#define PSTR 132
#define JT   144
#define IT   16
#define JTA  148

// ---------------- scratch (static device globals; no allocation) ----------
__device__ float g_buf[TT * DD];
__device__ float v_buf[TT * DD];
__device__ float norm_buf[NH * TT];
__device__ float denom_buf[NH * TT];
__device__ float suminv_buf[NH];
__device__ float p_buf[(size_t)NH * TT * PSTR];

__device__ __nv_bfloat16 xh_buf[TT * DD], xl_buf[TT * DD];
__device__ __nv_bfloat16 oh_buf[TT * DD], ol_buf[TT * DD];
__device__ __nv_bfloat16 wgh_buf[DD * DD], wgl_buf[DD * DD];
__device__ __nv_bfloat16 wvh_buf[DD * DD], wvl_buf[DD * DD];
__device__ __nv_bfloat16 woh_buf[DD * DD], wol_buf[DD * DD];

// ---------------- PTX helpers ----------------------------------------------
__device__ __forceinline__ uint32_t s2u(const void* p) {
    uint32_t a;
    asm("{ .reg .u64 t; cvta.to.shared.u64 t, %1; cvt.u32.u64 %0, t; }"
        : "=r"(a) : "l"(p));
    return a;
}
#define CP_ASYNC16(dst, src) \
    asm volatile("cp.async.cg.shared.global [%0], [%1], 16;" :: "r"(dst), "l"(src))
#define CP_COMMIT()  asm volatile("cp.async.commit_group;" ::: "memory")
#define CP_WAIT2()   asm volatile("cp.async.wait_group 2;" ::: "memory")
#define CP_WAIT1()   asm volatile("cp.async.wait_group 1;" ::: "memory")
#define CP_WAIT0()   asm volatile("cp.async.wait_group 0;" ::: "memory")

__device__ __forceinline__ void ldsm_x4(uint32_t& r0, uint32_t& r1,
                                        uint32_t& r2, uint32_t& r3, uint32_t a) {
    asm volatile("ldmatrix.sync.aligned.m8n8.x4.shared.b16 {%0,%1,%2,%3}, [%4];"
                 : "=r"(r0), "=r"(r1), "=r"(r2), "=r"(r3) : "r"(a));
}
__device__ __forceinline__ void mma16816(float* d, const uint32_t* a, const uint32_t* b) {
    asm volatile(
        "mma.sync.aligned.m16n8k16.row.col.f32.bf16.bf16.f32 "
        "{%0,%1,%2,%3}, {%4,%5,%6,%7}, {%8,%9}, {%0,%1,%2,%3};"
        : "+f"(d[0]), "+f"(d[1]), "+f"(d[2]), "+f"(d[3])
        : "r"(a[0]), "r"(a[1]), "r"(a[2]), "r"(a[3]), "r"(b[0]), "r"(b[1]));
}
__device__ __forceinline__ uint32_t sw64(uint32_t off) {
    return off ^ ((off >> 3) & 0x30u);
}

// ---------------- fp32->bf16 hi/lo split ------------------------------------
__device__ __forceinline__ void split_store(const float* __restrict__ src,
                                            __nv_bfloat16* __restrict__ dh,
                                            __nv_bfloat16* __restrict__ dl, int i)
{
    float4 v = ((const float4*)src)[i];
    __nv_bfloat16 h0 = __float2bfloat16(v.x), h1 = __float2bfloat16(v.y),
                  h2 = __float2bfloat16(v.z), h3 = __float2bfloat16(v.w);
    __nv_bfloat16 l0 = __float2bfloat16(v.x - __bfloat162float(h0)),
                  l1 = __float2bfloat16(v.y - __bfloat162float(h1)),
                  l2 = __float2bfloat16(v.z - __bfloat162float(h2)),
                  l3 = __float2bfloat16(v.w - __bfloat162float(h3));
    __nv_bfloat162 hp0(h0, h1), hp1(h2, h3), lp0(l0, l1), lp1(l2, l3);
    uint2 uh, ul;
    uh.x = *(unsigned*)&hp0; uh.y = *(unsigned*)&hp1;
    ul.x = *(unsigned*)&lp0; ul.y = *(unsigned*)&lp1;
    ((uint2*)dh)[i] = uh;
    ((uint2*)dl)[i] = ul;
}

__global__ void __launch_bounds__(256)
k_conv_x(const float* __restrict__ x)
{
    if (blockIdx.x == 0 && threadIdx.x < NH) suminv_buf[threadIdx.x] = 0.f;
    const int i = blockIdx.x * 256 + threadIdx.x;
    split_store(x, xh_buf, xl_buf, i);
}

__global__ void __launch_bounds__(256)
k_conv_wgv(const float* __restrict__ Wg, const float* __restrict__ Wv)
{
    const int i = (blockIdx.x & 1023) * 256 + threadIdx.x;
    if (blockIdx.x < 1024) split_store(Wg, wgh_buf, wgl_buf, i);
    else                   split_store(Wv, wvh_buf, wvl_buf, i);
}

__global__ void __launch_bounds__(256)
k_conv_wo(const float* __restrict__ Wo)
{
    const int i = blockIdx.x * 256 + threadIdx.x;
    split_store(Wo, woh_buf, wol_buf, i);
}

// ---------------- HMMA bf16-split GEMM --------------------------------------
#define KC32   32
#define NC     (DD / KC32)          // 32 chunks
#define ATSZ   8192                 // 128 rows x 64B
#define BTSZ   4096                 // 64 rows x 64B
#define STG    (2 * ATSZ + 2 * BTSZ)
#define NSTAGE 4
#define SMEM_G (NSTAGE * STG)       // 98304

__device__ __forceinline__ void load_stage(
    const uint4* __restrict__ Ah4, const uint4* __restrict__ Al4,
    const uint4* __restrict__ Bh4, const uint4* __restrict__ Bl4,
    uint32_t sb, int slot, int c, int m0, int n0, int tid)
{
    const uint32_t base = sb + slot * STG;
    const int q = tid & 3;
#pragma unroll
    for (int t = 0; t < 4; ++t) {
        const int row = (t * 64 + (tid >> 2)) & 127;
        const uint32_t dst = base + (t >> 1) * ATSZ + sw64((uint32_t)row * 64u + q * 16u);
        const uint4* src = ((t >> 1) ? Al4 : Ah4)
                         + (size_t)(m0 + row) * (DD / 8) + c * 4 + q;
        CP_ASYNC16(dst, src);
    }
#pragma unroll
    for (int t = 0; t < 2; ++t) {
        const int row = tid >> 2;
        const uint32_t dst = base + 2 * ATSZ + t * BTSZ
                           + sw64((uint32_t)row * 64u + q * 16u);
        const uint4* src = (t ? Bl4 : Bh4)
                         + (size_t)(n0 + row) * (DD / 8) + c * 4 + q;
        CP_ASYNC16(dst, src);
    }
}

__device__ __forceinline__ void gemm_core(
    const uint4* __restrict__ Ah4, const uint4* __restrict__ Al4,
    const uint4* __restrict__ Bh4, const uint4* __restrict__ Bl4,
    const float* __restrict__ bias, float* __restrict__ C, bool doNorm)
{
    extern __shared__ char smem[];
    __shared__ float ssrow[128];
    const uint32_t sb = s2u(smem);
    const int tid  = threadIdx.x;
    const int wid  = tid >> 5;
    const int lane = tid & 31;
    const int n0 = blockIdx.x * 64, m0 = blockIdx.y * 128;

    const int wm = wid >> 1;
    const int wn = wid & 1;

    const int r  = lane & 7;
    const int md = lane >> 3;
    const int rowA = wm * 32 + (md & 1) * 8 + r;
    const uint32_t bA = (md >> 1) * 16;
    const int rowB = wn * 32 + (md >> 1) * 8 + r;
    const uint32_t bB = (md & 1) * 16;

    if (doNorm && tid < 128) ssrow[tid] = 0.f;

    float acc[2][4][4];
#pragma unroll
    for (int f = 0; f < 2; ++f)
#pragma unroll
        for (int j = 0; j < 4; ++j)
#pragma unroll
            for (int e = 0; e < 4; ++e) acc[f][j][e] = 0.f;

    load_stage(Ah4, Al4, Bh4, Bl4, sb, 0, 0, m0, n0, tid); CP_COMMIT();
    load_stage(Ah4, Al4, Bh4, Bl4, sb, 1, 1, m0, n0, tid); CP_COMMIT();
    load_stage(Ah4, Al4, Bh4, Bl4, sb, 2, 2, m0, n0, tid); CP_COMMIT();

#pragma unroll 1
    for (int c = 0; c < NC; ++c) {
        const int rem = NC - 1 - c;
        if (rem >= 2) CP_WAIT2(); else if (rem == 1) CP_WAIT1(); else CP_WAIT0();
        __syncthreads();

        const uint32_t base = sb + (c & 3) * STG;
        const uint32_t stAh = base;
        const uint32_t stAl = base + ATSZ;
        const uint32_t stBh = base + 2 * ATSZ;
        const uint32_t stBl = base + 2 * ATSZ + BTSZ;

#pragma unroll
        for (int ks = 0; ks < 2; ++ks) {
            const uint32_t kb = ks * 32;
            uint32_t ah[2][4], al[2][4];
#pragma unroll
            for (int f = 0; f < 2; ++f) {
                const uint32_t off = sw64((uint32_t)(rowA + f * 16) * 64u + kb + bA);
                ldsm_x4(ah[f][0], ah[f][1], ah[f][2], ah[f][3], stAh + off);
                ldsm_x4(al[f][0], al[f][1], al[f][2], al[f][3], stAl + off);
            }
            uint32_t bh[4][2], bl[4][2];
#pragma unroll
            for (int p = 0; p < 2; ++p) {
                const uint32_t off = sw64((uint32_t)(rowB + p * 16) * 64u + kb + bB);
                ldsm_x4(bh[2*p][0], bh[2*p][1], bh[2*p+1][0], bh[2*p+1][1], stBh + off);
                ldsm_x4(bl[2*p][0], bl[2*p][1], bl[2*p+1][0], bl[2*p+1][1], stBl + off);
            }
#pragma unroll
            for (int f = 0; f < 2; ++f)
#pragma unroll
                for (int j = 0; j < 4; ++j) {
                    mma16816(acc[f][j], ah[f], bh[j]);
                    mma16816(acc[f][j], ah[f], bl[j]);
                    mma16816(acc[f][j], al[f], bh[j]);
                }
        }
        if (c + 3 < NC) {
            load_stage(Ah4, Al4, Bh4, Bl4, sb, (c + 3) & 3, c + 3, m0, n0, tid);
            CP_COMMIT();
        }
    }

    // epilogue (+ optional fused per-row sum of squares for norms)
#pragma unroll
    for (int f = 0; f < 2; ++f) {
        const int grow = m0 + wm * 32 + f * 16 + (lane >> 2);
        float* c0 = C + (size_t)grow * DD;
        float* c1 = c0 + 8 * DD;
        float ss0 = 0.f, ss1 = 0.f;
#pragma unroll
        for (int j = 0; j < 4; ++j) {
            const int col = n0 + wn * 32 + j * 8 + (lane & 3) * 2;
            const float2 bb = *(const float2*)(bias + col);
            float2 o0 = make_float2(acc[f][j][0] + bb.x, acc[f][j][1] + bb.y);
            float2 o1 = make_float2(acc[f][j][2] + bb.x, acc[f][j][3] + bb.y);
            *(float2*)(c0 + col) = o0;
            *(float2*)(c1 + col) = o1;
            ss0 = fmaf(o0.x, o0.x, fmaf(o0.y, o0.y, ss0));
            ss1 = fmaf(o1.x, o1.x, fmaf(o1.y, o1.y, ss1));
        }
        if (doNorm) {
            ss0 += __shfl_xor_sync(0xffffffffu, ss0, 1);
            ss0 += __shfl_xor_sync(0xffffffffu, ss0, 2);
            ss1 += __shfl_xor_sync(0xffffffffu, ss1, 1);
            ss1 += __shfl_xor_sync(0xffffffffu, ss1, 2);
            if ((lane & 3) == 0) {
                const int l0 = wm * 32 + f * 16 + (lane >> 2);
                atomicAdd(&ssrow[l0], ss0);
                atomicAdd(&ssrow[l0 + 8], ss1);
            }
        }
    }
    if (doNorm) {
        __syncthreads();
        if (tid < 128) {
            const int h = n0 >> 6;
            norm_buf[h * TT + m0 + tid] = sqrtf(ssrow[tid]);
        }
    }
}

__global__ void __launch_bounds__(256, 2)
k_gemm_gv(const float* __restrict__ bg, const float* __restrict__ bv)
{
    if (blockIdx.z == 0)
        gemm_core((const uint4*)xh_buf, (const uint4*)xl_buf,
                  (const uint4*)wgh_buf, (const uint4*)wgl_buf, bg, g_buf, true);
    else
        gemm_core((const uint4*)xh_buf, (const uint4*)xl_buf,
                  (const uint4*)wvh_buf, (const uint4*)wvl_buf, bv, v_buf, false);
}

__global__ void __launch_bounds__(256, 2)
k_gemm_o(const float* __restrict__ bo, float* __restrict__ out)
{
    gemm_core((const uint4*)oh_buf, (const uint4*)ol_buf,
              (const uint4*)woh_buf, (const uint4*)wol_buf, bo, out, false);
}

// ---------------- windowed scores + gene_means denom (8 rows / block) ------
__global__ void __launch_bounds__(256)
k_scores()
{
    const int i0 = blockIdx.x * 8;
    const int h  = blockIdx.y;
    const int tid = threadIdx.x;

    const int jstart0 = (i0 > WIN) ? (i0 - WIN) : 0;
    const int span    = (i0 + 7) - jstart0 + 1;

    __shared__ __align__(16) float4 gwT[16][JT];
    __shared__ float nw[JT];
    __shared__ float rowsum[8];

    const float4* g4 = (const float4*)g_buf;
    for (int idx = tid; idx < span * 16; idx += 256) {
        int jj = idx >> 4;
        int q  = idx & 15;
        gwT[q][jj] = g4[(size_t)(jstart0 + jj) * (DD / 4) + h * (HDIM / 4) + q];
    }
    for (int idx = tid; idx < span; idx += 256)
        nw[idx] = norm_buf[h * TT + jstart0 + idx];
    if (tid < 8) rowsum[tid] = 0.f;
    __syncthreads();

    const int group = tid >> 7;
    const int jl    = tid & 127;
    const int ibase = i0 + group * 4;
    const int wi0   = ibase - jstart0;

    float psum[4] = {0.f, 0.f, 0.f, 0.f};

    for (int jj = jl; jj < span; jj += 128) {
        float dot[4] = {0.f, 0.f, 0.f, 0.f};
#pragma unroll
        for (int q = 0; q < 16; ++q) {
            float4 b = gwT[q][jj];
#pragma unroll
            for (int r = 0; r < 4; ++r) {
                float4 a = gwT[q][wi0 + r];
                dot[r] = fmaf(a.x, b.x, dot[r]);
                dot[r] = fmaf(a.y, b.y, dot[r]);
                dot[r] = fmaf(a.z, b.z, dot[r]);
                dot[r] = fmaf(a.w, b.w, dot[r]);
            }
        }
        float njj = nw[jj];
#pragma unroll
        for (int r = 0; r < 4; ++r) {
            const int i   = ibase + r;
            const int wi  = wi0 + r;
            const int off = ((i > WIN) ? (i - WIN) : 0) - jstart0;
            if (jj >= off && jj <= wi) {
                float c = dot[r] / (nw[wi] * njj + 1e-8f);
                if (c != c) c = 0.f;
                float p = (c + 1.f) * 0.5f;
                p_buf[(size_t)(h * TT + i) * PSTR + (jj - off)] = p;
                psum[r] += p;
            }
        }
    }

#pragma unroll
    for (int r = 0; r < 4; ++r) {
        float s = psum[r];
#pragma unroll
        for (int o = 16; o > 0; o >>= 1) s += __shfl_xor_sync(0xffffffffu, s, o);
        if ((tid & 31) == 0) atomicAdd(&rowsum[group * 4 + r], s);
    }
    __syncthreads();

    if (tid < 8) {
        const int i   = i0 + tid;
        const int cnt = i - ((i > WIN) ? (i - WIN) : 0) + 1;
        float gm = (rowsum[tid] + 0.5f * (float)(TT - cnt)) * (1.f / (float)TT);
        float dn = gm + 0.5f;
        denom_buf[h * TT + i] = dn;
        atomicAdd(&suminv_buf[h], 1.f / dn);
    }
}

// ---------------- softmax + attn@v (16 rows / block), emits bf16 hi/lo -----
#define SATT_STRIDE 20
#define ATTN_SMEM   (JTA * HDIM * 4 + JTA * SATT_STRIDE * 4 + 4 * IT * HDIM * 4 + 64)

__global__ void __launch_bounds__(256)
k_attnv()
{
    extern __shared__ char dynsm[];
    float (*vw)[HDIM]       = (float(*)[HDIM])dynsm;
    float (*sattn)[SATT_STRIDE] =
        (float(*)[SATT_STRIDE])(dynsm + JTA * HDIM * 4);
    float (*red)[IT][HDIM]  =
        (float(*)[IT][HDIM])(dynsm + JTA * HDIM * 4 + JTA * SATT_STRIDE * 4);
    float* invs = (float*)(dynsm + JTA * HDIM * 4 + JTA * SATT_STRIDE * 4
                           + 4 * IT * HDIM * 4);

    const int i0  = blockIdx.x * IT;
    const int h   = blockIdx.y;
    const int tid = threadIdx.x;
    const int wid = tid >> 5;
    const int lane = tid & 31;

    const int jstart0 = (i0 > WIN) ? (i0 - WIN) : 0;
    const int span    = (i0 + IT - 1) - jstart0 + 1;

    const float4* v4 = (const float4*)v_buf;
    for (int idx = tid; idx < span * 16; idx += 256) {
        int jj = idx >> 4;
        int q  = idx & 15;
        ((float4*)&vw[jj][0])[q] = v4[(size_t)(jstart0 + jj) * (DD / 4) + h * (HDIM / 4) + q];
    }
    __syncthreads();

#pragma unroll
    for (int rr = 0; rr < 2; ++rr) {
        const int w = wid + rr * 8;
        const int i = i0 + w;
        const size_t row = (size_t)h * TT + i;
        const float fit  = 1.f / (denom_buf[row] * suminv_buf[h]);
        const int off = ((i > WIN) ? (i - WIN) : 0) - jstart0;
        const int wi  = i - jstart0;

        float m = -1e30f;
        for (int q = lane; q < JTA; q += 32) {
            bool in = (q >= off) && (q <= wi);
            float s = in ? fit * p_buf[row * PSTR + (q - off)] : -1e30f;
            sattn[q][w] = s;
            m = fmaxf(m, s);
        }
#pragma unroll
        for (int o = 16; o > 0; o >>= 1) m = fmaxf(m, __shfl_xor_sync(0xffffffffu, m, o));

        float ss = 0.f;
        for (int q = lane; q < JTA; q += 32) {
            float e = expf(sattn[q][w] - m);
            sattn[q][w] = e;
            ss += e;
        }
#pragma unroll
        for (int o = 16; o > 0; o >>= 1) ss += __shfl_xor_sync(0xffffffffu, ss, o);
        if (lane == 0) invs[w] = 1.f / ss;
    }
    __syncthreads();

    {
        const int d  = tid & 63;
        const int qq = tid >> 6;
        float acc[IT];
#pragma unroll
        for (int w = 0; w < IT; ++w) acc[w] = 0.f;

        for (int jj = qq; jj < span; jj += 4) {
            const float vv = vw[jj][d];
            const float4 s0 = *(const float4*)&sattn[jj][0];
            const float4 s1 = *(const float4*)&sattn[jj][4];
            const float4 s2 = *(const float4*)&sattn[jj][8];
            const float4 s3 = *(const float4*)&sattn[jj][12];
            acc[0]  = fmaf(s0.x, vv, acc[0]);  acc[1]  = fmaf(s0.y, vv, acc[1]);
            acc[2]  = fmaf(s0.z, vv, acc[2]);  acc[3]  = fmaf(s0.w, vv, acc[3]);
            acc[4]  = fmaf(s1.x, vv, acc[4]);  acc[5]  = fmaf(s1.y, vv, acc[5]);
            acc[6]  = fmaf(s1.z, vv, acc[6]);  acc[7]  = fmaf(s1.w, vv, acc[7]);
            acc[8]  = fmaf(s2.x, vv, acc[8]);  acc[9]  = fmaf(s2.y, vv, acc[9]);
            acc[10] = fmaf(s2.z, vv, acc[10]); acc[11] = fmaf(s2.w, vv, acc[11]);
            acc[12] = fmaf(s3.x, vv, acc[12]); acc[13] = fmaf(s3.y, vv, acc[13]);
            acc[14] = fmaf(s3.z, vv, acc[14]); acc[15] = fmaf(s3.w, vv, acc[15]);
        }
#pragma unroll
        for (int w = 0; w < IT; ++w) red[qq][w][d] = acc[w];
        __syncthreads();

        if (qq == 0) {
#pragma unroll
            for (int w = 0; w < IT; ++w) {
                float s = (red[0][w][d] + red[1][w][d]) + (red[2][w][d] + red[3][w][d]);
                float val = s * invs[w];
                const size_t idx = (size_t)(i0 + w) * DD + h * HDIM + d;
                __nv_bfloat16 hv = __float2bfloat16(val);
                __nv_bfloat16 lv = __float2bfloat16(val - __bfloat162float(hv));
                oh_buf[idx] = hv;
                ol_buf[idx] = lv;
            }
        }
    }
}

// ---------------- launch ---------------------------------------------------
extern "C" void kernel_launch(void* const* d_in, const int* in_sizes, int n_in,
                              void* d_out, int out_size)
{
    const float* x  = (const float*)d_in[0];
    const float* Wg = (const float*)d_in[1];
    const float* bg = (const float*)d_in[2];
    const float* Wv = (const float*)d_in[3];
    const float* bv = (const float*)d_in[4];
    const float* Wo = (const float*)d_in[5];
    const float* bo = (const float*)d_in[6];
    float* out = (float*)d_out;

    cudaFuncSetAttribute(k_gemm_gv, cudaFuncAttributeMaxDynamicSharedMemorySize, SMEM_G);
    cudaFuncSetAttribute(k_gemm_o,  cudaFuncAttributeMaxDynamicSharedMemorySize, SMEM_G);
    cudaFuncSetAttribute(k_attnv,   cudaFuncAttributeMaxDynamicSharedMemorySize, ATTN_SMEM);

    // launch #1..#3: conversions
    k_conv_x  <<<(TT * DD) / 1024, 256>>>(x);
    k_conv_wgv<<<(2 * DD * DD) / 1024, 256>>>(Wg, Wv);
    k_conv_wo <<<(DD * DD) / 1024, 256>>>(Wo);

    // launch #4: the big GEMM (lands on ncu's sampled slot)
    dim3 gemm_gv(DD / 64, TT / 128, 2);
    k_gemm_gv<<<gemm_gv, 256, SMEM_G>>>(bg, bv);

    dim3 sc_grid(TT / 8, NH);
    k_scores<<<sc_grid, 256>>>();

    dim3 av_grid(TT / IT, NH);
    k_attnv<<<av_grid, 256, ATTN_SMEM>>>();

    dim3 gemm_o(DD / 64, TT / 128, 1);
    k_gemm_o<<<gemm_o, 256, SMEM_G>>>(bo, out);
}

// round 8
// speedup vs baseline: 1.5138x; 1.5138x over previous
#include <cuda_runtime.h>
#include <cuda_bf16.h>
#include <math.h>
#include <stdint.h>

#define TT   2048
#define DD   1024
#define NH   16
#define HDIM 64
#define WIN  128
#define PSTR 132
#define IT   16
#define JTA  148
#define SIT  64     // scores i-tile
#define SPAN 192    // scores j-window (64 + 128)

// ---------------- scratch (static device globals; no allocation) ----------
__device__ float v_buf[TT * DD];
__device__ float norm_buf[NH * TT];
__device__ float denom_buf[NH * TT];
__device__ float suminv_buf[NH];
__device__ float p_buf[(size_t)NH * TT * PSTR];

__device__ __nv_bfloat16 xh_buf[TT * DD], xl_buf[TT * DD];
__device__ __nv_bfloat16 gh_buf[TT * DD], gl_buf[TT * DD];
__device__ __nv_bfloat16 oh_buf[TT * DD], ol_buf[TT * DD];
__device__ __nv_bfloat16 wgh_buf[DD * DD], wgl_buf[DD * DD];
__device__ __nv_bfloat16 wvh_buf[DD * DD], wvl_buf[DD * DD];
__device__ __nv_bfloat16 woh_buf[DD * DD], wol_buf[DD * DD];

// ---------------- PTX helpers ----------------------------------------------
__device__ __forceinline__ uint32_t s2u(const void* p) {
    uint32_t a;
    asm("{ .reg .u64 t; cvta.to.shared.u64 t, %1; cvt.u32.u64 %0, t; }"
        : "=r"(a) : "l"(p));
    return a;
}
#define CP_ASYNC16(dst, src) \
    asm volatile("cp.async.cg.shared.global [%0], [%1], 16;" :: "r"(dst), "l"(src))
#define CP_COMMIT()  asm volatile("cp.async.commit_group;" ::: "memory")
#define CP_WAIT2()   asm volatile("cp.async.wait_group 2;" ::: "memory")
#define CP_WAIT1()   asm volatile("cp.async.wait_group 1;" ::: "memory")
#define CP_WAIT0()   asm volatile("cp.async.wait_group 0;" ::: "memory")

__device__ __forceinline__ void ldsm_x4(uint32_t& r0, uint32_t& r1,
                                        uint32_t& r2, uint32_t& r3, uint32_t a) {
    asm volatile("ldmatrix.sync.aligned.m8n8.x4.shared.b16 {%0,%1,%2,%3}, [%4];"
                 : "=r"(r0), "=r"(r1), "=r"(r2), "=r"(r3) : "r"(a));
}
__device__ __forceinline__ void mma16816(float* d, const uint32_t* a, const uint32_t* b) {
    asm volatile(
        "mma.sync.aligned.m16n8k16.row.col.f32.bf16.bf16.f32 "
        "{%0,%1,%2,%3}, {%4,%5,%6,%7}, {%8,%9}, {%0,%1,%2,%3};"
        : "+f"(d[0]), "+f"(d[1]), "+f"(d[2]), "+f"(d[3])
        : "r"(a[0]), "r"(a[1]), "r"(a[2]), "r"(a[3]), "r"(b[0]), "r"(b[1]));
}
__device__ __forceinline__ uint32_t sw64(uint32_t off) {
    return off ^ ((off >> 3) & 0x30u);
}
__device__ __forceinline__ uint32_t sw128(uint32_t off) {
    return off ^ ((off >> 3) & 0x70u);
}

// ---------------- fp32->bf16 hi/lo split ------------------------------------
__device__ __forceinline__ void split_store(const float* __restrict__ src,
                                            __nv_bfloat16* __restrict__ dh,
                                            __nv_bfloat16* __restrict__ dl, int i)
{
    float4 v = ((const float4*)src)[i];
    __nv_bfloat16 h0 = __float2bfloat16(v.x), h1 = __float2bfloat16(v.y),
                  h2 = __float2bfloat16(v.z), h3 = __float2bfloat16(v.w);
    __nv_bfloat16 l0 = __float2bfloat16(v.x - __bfloat162float(h0)),
                  l1 = __float2bfloat16(v.y - __bfloat162float(h1)),
                  l2 = __float2bfloat16(v.z - __bfloat162float(h2)),
                  l3 = __float2bfloat16(v.w - __bfloat162float(h3));
    __nv_bfloat162 hp0(h0, h1), hp1(h2, h3), lp0(l0, l1), lp1(l2, l3);
    uint2 uh, ul;
    uh.x = *(unsigned*)&hp0; uh.y = *(unsigned*)&hp1;
    ul.x = *(unsigned*)&lp0; ul.y = *(unsigned*)&lp1;
    ((uint2*)dh)[i] = uh;
    ((uint2*)dl)[i] = ul;
}

__global__ void __launch_bounds__(256)
k_conv_x(const float* __restrict__ x)
{
    if (blockIdx.x == 0 && threadIdx.x < NH) suminv_buf[threadIdx.x] = 0.f;
    const int i = blockIdx.x * 256 + threadIdx.x;
    split_store(x, xh_buf, xl_buf, i);
}

__global__ void __launch_bounds__(256)
k_conv_wgv(const float* __restrict__ Wg, const float* __restrict__ Wv)
{
    const int i = (blockIdx.x & 1023) * 256 + threadIdx.x;
    if (blockIdx.x < 1024) split_store(Wg, wgh_buf, wgl_buf, i);
    else                   split_store(Wv, wvh_buf, wvl_buf, i);
}

__global__ void __launch_bounds__(256)
k_conv_wo(const float* __restrict__ Wo)
{
    const int i = blockIdx.x * 256 + threadIdx.x;
    split_store(Wo, woh_buf, wol_buf, i);
}

// ---------------- HMMA bf16-split GEMM --------------------------------------
#define KC32   32
#define NC     (DD / KC32)
#define ATSZ   8192
#define BTSZ   4096
#define STG    (2 * ATSZ + 2 * BTSZ)
#define NSTAGE 4
#define SMEM_G (NSTAGE * STG)

__device__ __forceinline__ void load_stage(
    const uint4* __restrict__ Ah4, const uint4* __restrict__ Al4,
    const uint4* __restrict__ Bh4, const uint4* __restrict__ Bl4,
    uint32_t sb, int slot, int c, int m0, int n0, int tid)
{
    const uint32_t base = sb + slot * STG;
    const int q = tid & 3;
#pragma unroll
    for (int t = 0; t < 4; ++t) {
        const int row = (t * 64 + (tid >> 2)) & 127;
        const uint32_t dst = base + (t >> 1) * ATSZ + sw64((uint32_t)row * 64u + q * 16u);
        const uint4* src = ((t >> 1) ? Al4 : Ah4)
                         + (size_t)(m0 + row) * (DD / 8) + c * 4 + q;
        CP_ASYNC16(dst, src);
    }
#pragma unroll
    for (int t = 0; t < 2; ++t) {
        const int row = tid >> 2;
        const uint32_t dst = base + 2 * ATSZ + t * BTSZ
                           + sw64((uint32_t)row * 64u + q * 16u);
        const uint4* src = (t ? Bl4 : Bh4)
                         + (size_t)(n0 + row) * (DD / 8) + c * 4 + q;
        CP_ASYNC16(dst, src);
    }
}

// doNorm: g-branch — emit bf16 hi/lo into gh/gl + per-row L2 norms (no fp32 C)
__device__ __forceinline__ void gemm_core(
    const uint4* __restrict__ Ah4, const uint4* __restrict__ Al4,
    const uint4* __restrict__ Bh4, const uint4* __restrict__ Bl4,
    const float* __restrict__ bias, float* __restrict__ C, bool doNorm)
{
    extern __shared__ char smem[];
    __shared__ float ssrow[128];
    const uint32_t sb = s2u(smem);
    const int tid  = threadIdx.x;
    const int wid  = tid >> 5;
    const int lane = tid & 31;
    const int n0 = blockIdx.x * 64, m0 = blockIdx.y * 128;

    const int wm = wid >> 1;
    const int wn = wid & 1;

    const int r  = lane & 7;
    const int md = lane >> 3;
    const int rowA = wm * 32 + (md & 1) * 8 + r;
    const uint32_t bA = (md >> 1) * 16;
    const int rowB = wn * 32 + (md >> 1) * 8 + r;
    const uint32_t bB = (md & 1) * 16;

    if (doNorm && tid < 128) ssrow[tid] = 0.f;

    float acc[2][4][4];
#pragma unroll
    for (int f = 0; f < 2; ++f)
#pragma unroll
        for (int j = 0; j < 4; ++j)
#pragma unroll
            for (int e = 0; e < 4; ++e) acc[f][j][e] = 0.f;

    load_stage(Ah4, Al4, Bh4, Bl4, sb, 0, 0, m0, n0, tid); CP_COMMIT();
    load_stage(Ah4, Al4, Bh4, Bl4, sb, 1, 1, m0, n0, tid); CP_COMMIT();
    load_stage(Ah4, Al4, Bh4, Bl4, sb, 2, 2, m0, n0, tid); CP_COMMIT();

#pragma unroll 1
    for (int c = 0; c < NC; ++c) {
        const int rem = NC - 1 - c;
        if (rem >= 2) CP_WAIT2(); else if (rem == 1) CP_WAIT1(); else CP_WAIT0();
        __syncthreads();

        const uint32_t base = sb + (c & 3) * STG;
        const uint32_t stAh = base;
        const uint32_t stAl = base + ATSZ;
        const uint32_t stBh = base + 2 * ATSZ;
        const uint32_t stBl = base + 2 * ATSZ + BTSZ;

#pragma unroll
        for (int ks = 0; ks < 2; ++ks) {
            const uint32_t kb = ks * 32;
            uint32_t ah[2][4], al[2][4];
#pragma unroll
            for (int f = 0; f < 2; ++f) {
                const uint32_t off = sw64((uint32_t)(rowA + f * 16) * 64u + kb + bA);
                ldsm_x4(ah[f][0], ah[f][1], ah[f][2], ah[f][3], stAh + off);
                ldsm_x4(al[f][0], al[f][1], al[f][2], al[f][3], stAl + off);
            }
            uint32_t bh[4][2], bl[4][2];
#pragma unroll
            for (int p = 0; p < 2; ++p) {
                const uint32_t off = sw64((uint32_t)(rowB + p * 16) * 64u + kb + bB);
                ldsm_x4(bh[2*p][0], bh[2*p][1], bh[2*p+1][0], bh[2*p+1][1], stBh + off);
                ldsm_x4(bl[2*p][0], bl[2*p][1], bl[2*p+1][0], bl[2*p+1][1], stBl + off);
            }
#pragma unroll
            for (int f = 0; f < 2; ++f)
#pragma unroll
                for (int j = 0; j < 4; ++j) {
                    mma16816(acc[f][j], ah[f], bh[j]);
                    mma16816(acc[f][j], ah[f], bl[j]);
                    mma16816(acc[f][j], al[f], bh[j]);
                }
        }
        if (c + 3 < NC) {
            load_stage(Ah4, Al4, Bh4, Bl4, sb, (c + 3) & 3, c + 3, m0, n0, tid);
            CP_COMMIT();
        }
    }

    // epilogue
#pragma unroll
    for (int f = 0; f < 2; ++f) {
        const int grow = m0 + wm * 32 + f * 16 + (lane >> 2);
        float ss0 = 0.f, ss1 = 0.f;
#pragma unroll
        for (int j = 0; j < 4; ++j) {
            const int col = n0 + wn * 32 + j * 8 + (lane & 3) * 2;
            const float2 bb = *(const float2*)(bias + col);
            float2 o0 = make_float2(acc[f][j][0] + bb.x, acc[f][j][1] + bb.y);
            float2 o1 = make_float2(acc[f][j][2] + bb.x, acc[f][j][3] + bb.y);
            if (doNorm) {
                // bf16 hi/lo split store of g
                const size_t p0 = ((size_t)grow * DD + col) >> 1;
                const size_t p1 = ((size_t)(grow + 8) * DD + col) >> 1;
                __nv_bfloat16 h00 = __float2bfloat16(o0.x), h01 = __float2bfloat16(o0.y);
                __nv_bfloat16 h10 = __float2bfloat16(o1.x), h11 = __float2bfloat16(o1.y);
                __nv_bfloat16 l00 = __float2bfloat16(o0.x - __bfloat162float(h00));
                __nv_bfloat16 l01 = __float2bfloat16(o0.y - __bfloat162float(h01));
                __nv_bfloat16 l10 = __float2bfloat16(o1.x - __bfloat162float(h10));
                __nv_bfloat16 l11 = __float2bfloat16(o1.y - __bfloat162float(h11));
                ((__nv_bfloat162*)gh_buf)[p0] = __nv_bfloat162(h00, h01);
                ((__nv_bfloat162*)gl_buf)[p0] = __nv_bfloat162(l00, l01);
                ((__nv_bfloat162*)gh_buf)[p1] = __nv_bfloat162(h10, h11);
                ((__nv_bfloat162*)gl_buf)[p1] = __nv_bfloat162(l10, l11);
                ss0 = fmaf(o0.x, o0.x, fmaf(o0.y, o0.y, ss0));
                ss1 = fmaf(o1.x, o1.x, fmaf(o1.y, o1.y, ss1));
            } else {
                float* c0 = C + (size_t)grow * DD;
                *(float2*)(c0 + col) = o0;
                *(float2*)(c0 + 8 * DD + col) = o1;
            }
        }
        if (doNorm) {
            ss0 += __shfl_xor_sync(0xffffffffu, ss0, 1);
            ss0 += __shfl_xor_sync(0xffffffffu, ss0, 2);
            ss1 += __shfl_xor_sync(0xffffffffu, ss1, 1);
            ss1 += __shfl_xor_sync(0xffffffffu, ss1, 2);
            if ((lane & 3) == 0) {
                const int l0 = wm * 32 + f * 16 + (lane >> 2);
                atomicAdd(&ssrow[l0], ss0);
                atomicAdd(&ssrow[l0 + 8], ss1);
            }
        }
    }
    if (doNorm) {
        __syncthreads();
        if (tid < 128) {
            const int h = n0 >> 6;
            norm_buf[h * TT + m0 + tid] = sqrtf(ssrow[tid]);
        }
    }
}

__global__ void __launch_bounds__(256, 2)
k_gemm_gv(const float* __restrict__ bg, const float* __restrict__ bv)
{
    if (blockIdx.z == 0)
        gemm_core((const uint4*)xh_buf, (const uint4*)xl_buf,
                  (const uint4*)wgh_buf, (const uint4*)wgl_buf, bg, nullptr, true);
    else
        gemm_core((const uint4*)xh_buf, (const uint4*)xl_buf,
                  (const uint4*)wvh_buf, (const uint4*)wvl_buf, bv, v_buf, false);
}

__global__ void __launch_bounds__(256, 2)
k_gemm_o(const float* __restrict__ bo, float* __restrict__ out)
{
    gemm_core((const uint4*)oh_buf, (const uint4*)ol_buf,
              (const uint4*)woh_buf, (const uint4*)wol_buf, bo, out, false);
}

// ---------------- MMA banded scores: S = G·G^T on the 129-band --------------
// Tile: 64 i-rows x 192 j-window, 8 warps = 4(m16) x 2(n96).
#define WTSZ   (SPAN * 128)            // 24576 B per hi/lo window
#define SMEM_S (2 * WTSZ)

__global__ void __launch_bounds__(256)
k_scores_mma()
{
    extern __shared__ char smem[];
    __shared__ float nwin[SPAN];
    __shared__ float rowsum[SIT];

    const uint32_t sbH = s2u(smem);
    const uint32_t sbL = sbH + WTSZ;
    const int tid  = threadIdx.x;
    const int wid  = tid >> 5;
    const int lane = tid & 31;
    const int i0 = blockIdx.x * SIT;
    const int h  = blockIdx.y;

    const int jstart0 = (i0 > WIN) ? (i0 - WIN) : 0;
    const int qbase   = i0 - jstart0;          // 0..128

    // load window (192 rows x 128B) of gh/gl, SW128-swizzled
    const uint4* gh4 = (const uint4*)gh_buf;
    const uint4* gl4 = (const uint4*)gl_buf;
#pragma unroll
    for (int t = 0; t < 6; ++t) {
        const int idx = t * 256 + tid;         // 0..1535 = 192*8
        const int row = idx >> 3;
        const int q   = idx & 7;
        const uint32_t d = sw128((uint32_t)row * 128u + q * 16u);
        const size_t g = (size_t)(jstart0 + row) * (DD / 8) + h * 8 + q;
        CP_ASYNC16(sbH + d, gh4 + g);
        CP_ASYNC16(sbL + d, gl4 + g);
    }
    CP_COMMIT();
    if (tid < SPAN) nwin[tid] = norm_buf[h * TT + jstart0 + tid];
    if (tid < SIT) rowsum[tid] = 0.f;
    CP_WAIT0();
    __syncthreads();

    const int wm = wid >> 1;                   // 0..3: m16 tile
    const int wn = wid & 1;                    // 0..1: n96 half

    const int r  = lane & 7;
    const int md = lane >> 3;
    const int arow  = qbase + wm * 16 + (md & 1) * 8 + r;
    const uint32_t abyte = (md >> 1) * 16;
    const int brow0 = wn * 96 + (md >> 1) * 8 + r;
    const uint32_t bbyte = (md & 1) * 16;

    float acc[12][4];
#pragma unroll
    for (int nt = 0; nt < 12; ++nt)
#pragma unroll
        for (int e = 0; e < 4; ++e) acc[nt][e] = 0.f;

#pragma unroll
    for (int ks = 0; ks < 4; ++ks) {
        const uint32_t kb = ks * 32;
        uint32_t ah[4], al[4];
        const uint32_t aoff = sw128((uint32_t)arow * 128u + kb + abyte);
        ldsm_x4(ah[0], ah[1], ah[2], ah[3], sbH + aoff);
        ldsm_x4(al[0], al[1], al[2], al[3], sbL + aoff);
#pragma unroll
        for (int bt = 0; bt < 6; ++bt) {
            uint32_t bh[2][2], bl[2][2];
            const uint32_t boff = sw128((uint32_t)(brow0 + bt * 16) * 128u + kb + bbyte);
            ldsm_x4(bh[0][0], bh[0][1], bh[1][0], bh[1][1], sbH + boff);
            ldsm_x4(bl[0][0], bl[0][1], bl[1][0], bl[1][1], sbL + boff);
#pragma unroll
            for (int p = 0; p < 2; ++p) {
                mma16816(acc[2*bt + p], ah, bh[p]);
                mma16816(acc[2*bt + p], ah, bl[p]);
                mma16816(acc[2*bt + p], al, bh[p]);
            }
        }
    }

    // epilogue: cosine, mask, p, store + rowsums
    const int quad = lane >> 2;
    const int cp2  = (lane & 3) * 2;
    const int gi0 = i0 + wm * 16 + quad;
    const int gi1 = gi0 + 8;
    const float ni0 = nwin[qbase + wm * 16 + quad];
    const float ni1 = nwin[qbase + wm * 16 + quad + 8];
    const int off0 = (gi0 > WIN) ? (gi0 - WIN) : 0;
    const int off1 = (gi1 > WIN) ? (gi1 - WIN) : 0;
    float* pr0 = p_buf + (size_t)(h * TT + gi0) * PSTR;
    float* pr1 = p_buf + (size_t)(h * TT + gi1) * PSTR;
    float ps0 = 0.f, ps1 = 0.f;

#pragma unroll
    for (int nt = 0; nt < 12; ++nt) {
        const int jl = wn * 96 + nt * 8 + cp2;
        const int jg = jstart0 + jl;
        const float nj0 = nwin[jl];
        const float nj1 = nwin[jl + 1];
#pragma unroll
        for (int e = 0; e < 4; ++e) {
            const int  jj = jg + (e & 1);
            const float nj = (e & 1) ? nj1 : nj0;
            const int  gi  = (e >> 1) ? gi1 : gi0;
            const float ni = (e >> 1) ? ni1 : ni0;
            const int  off = (e >> 1) ? off1 : off0;
            if (jj <= gi && jj >= off) {
                float c = acc[nt][e] / (ni * nj + 1e-8f);
                if (c != c) c = 0.f;
                float p = (c + 1.f) * 0.5f;
                ((e >> 1) ? pr1 : pr0)[jj - off] = p;
                if (e >> 1) ps1 += p; else ps0 += p;
            }
        }
    }

    ps0 += __shfl_xor_sync(0xffffffffu, ps0, 1);
    ps0 += __shfl_xor_sync(0xffffffffu, ps0, 2);
    ps1 += __shfl_xor_sync(0xffffffffu, ps1, 1);
    ps1 += __shfl_xor_sync(0xffffffffu, ps1, 2);
    if ((lane & 3) == 0) {
        atomicAdd(&rowsum[wm * 16 + quad], ps0);
        atomicAdd(&rowsum[wm * 16 + quad + 8], ps1);
    }
    __syncthreads();

    if (tid < SIT) {
        const int i   = i0 + tid;
        const int cnt = i - ((i > WIN) ? (i - WIN) : 0) + 1;
        float gm = (rowsum[tid] + 0.5f * (float)(TT - cnt)) * (1.f / (float)TT);
        float dn = gm + 0.5f;
        denom_buf[h * TT + i] = dn;
        atomicAdd(&suminv_buf[h], 1.f / dn);
    }
}

// ---------------- softmax + attn@v (16 rows / block), emits bf16 hi/lo -----
#define SATT_STRIDE 20
#define ATTN_SMEM   (JTA * HDIM * 4 + JTA * SATT_STRIDE * 4 + 4 * IT * HDIM * 4 + 64)

__global__ void __launch_bounds__(256)
k_attnv()
{
    extern __shared__ char dynsm[];
    float (*vw)[HDIM]       = (float(*)[HDIM])dynsm;
    float (*sattn)[SATT_STRIDE] =
        (float(*)[SATT_STRIDE])(dynsm + JTA * HDIM * 4);
    float (*red)[IT][HDIM]  =
        (float(*)[IT][HDIM])(dynsm + JTA * HDIM * 4 + JTA * SATT_STRIDE * 4);
    float* invs = (float*)(dynsm + JTA * HDIM * 4 + JTA * SATT_STRIDE * 4
                           + 4 * IT * HDIM * 4);

    const int i0  = blockIdx.x * IT;
    const int h   = blockIdx.y;
    const int tid = threadIdx.x;
    const int wid = tid >> 5;
    const int lane = tid & 31;

    const int jstart0 = (i0 > WIN) ? (i0 - WIN) : 0;
    const int span    = (i0 + IT - 1) - jstart0 + 1;

    const float4* v4 = (const float4*)v_buf;
    for (int idx = tid; idx < span * 16; idx += 256) {
        int jj = idx >> 4;
        int q  = idx & 15;
        ((float4*)&vw[jj][0])[q] = v4[(size_t)(jstart0 + jj) * (DD / 4) + h * (HDIM / 4) + q];
    }
    __syncthreads();

#pragma unroll
    for (int rr = 0; rr < 2; ++rr) {
        const int w = wid + rr * 8;
        const int i = i0 + w;
        const size_t row = (size_t)h * TT + i;
        const float fit  = 1.f / (denom_buf[row] * suminv_buf[h]);
        const int off = ((i > WIN) ? (i - WIN) : 0) - jstart0;
        const int wi  = i - jstart0;

        float m = -1e30f;
        for (int q = lane; q < JTA; q += 32) {
            bool in = (q >= off) && (q <= wi);
            float s = in ? fit * p_buf[row * PSTR + (q - off)] : -1e30f;
            sattn[q][w] = s;
            m = fmaxf(m, s);
        }
#pragma unroll
        for (int o = 16; o > 0; o >>= 1) m = fmaxf(m, __shfl_xor_sync(0xffffffffu, m, o));

        float ss = 0.f;
        for (int q = lane; q < JTA; q += 32) {
            float e = expf(sattn[q][w] - m);
            sattn[q][w] = e;
            ss += e;
        }
#pragma unroll
        for (int o = 16; o > 0; o >>= 1) ss += __shfl_xor_sync(0xffffffffu, ss, o);
        if (lane == 0) invs[w] = 1.f / ss;
    }
    __syncthreads();

    {
        const int d  = tid & 63;
        const int qq = tid >> 6;
        float acc[IT];
#pragma unroll
        for (int w = 0; w < IT; ++w) acc[w] = 0.f;

        for (int jj = qq; jj < span; jj += 4) {
            const float vv = vw[jj][d];
            const float4 s0 = *(const float4*)&sattn[jj][0];
            const float4 s1 = *(const float4*)&sattn[jj][4];
            const float4 s2 = *(const float4*)&sattn[jj][8];
            const float4 s3 = *(const float4*)&sattn[jj][12];
            acc[0]  = fmaf(s0.x, vv, acc[0]);  acc[1]  = fmaf(s0.y, vv, acc[1]);
            acc[2]  = fmaf(s0.z, vv, acc[2]);  acc[3]  = fmaf(s0.w, vv, acc[3]);
            acc[4]  = fmaf(s1.x, vv, acc[4]);  acc[5]  = fmaf(s1.y, vv, acc[5]);
            acc[6]  = fmaf(s1.z, vv, acc[6]);  acc[7]  = fmaf(s1.w, vv, acc[7]);
            acc[8]  = fmaf(s2.x, vv, acc[8]);  acc[9]  = fmaf(s2.y, vv, acc[9]);
            acc[10] = fmaf(s2.z, vv, acc[10]); acc[11] = fmaf(s2.w, vv, acc[11]);
            acc[12] = fmaf(s3.x, vv, acc[12]); acc[13] = fmaf(s3.y, vv, acc[13]);
            acc[14] = fmaf(s3.z, vv, acc[14]); acc[15] = fmaf(s3.w, vv, acc[15]);
        }
#pragma unroll
        for (int w = 0; w < IT; ++w) red[qq][w][d] = acc[w];
        __syncthreads();

        if (qq == 0) {
#pragma unroll
            for (int w = 0; w < IT; ++w) {
                float s = (red[0][w][d] + red[1][w][d]) + (red[2][w][d] + red[3][w][d]);
                float val = s * invs[w];
                const size_t idx = (size_t)(i0 + w) * DD + h * HDIM + d;
                __nv_bfloat16 hv = __float2bfloat16(val);
                __nv_bfloat16 lv = __float2bfloat16(val - __bfloat162float(hv));
                oh_buf[idx] = hv;
                ol_buf[idx] = lv;
            }
        }
    }
}

// ---------------- launch ---------------------------------------------------
extern "C" void kernel_launch(void* const* d_in, const int* in_sizes, int n_in,
                              void* d_out, int out_size)
{
    const float* x  = (const float*)d_in[0];
    const float* Wg = (const float*)d_in[1];
    const float* bg = (const float*)d_in[2];
    const float* Wv = (const float*)d_in[3];
    const float* bv = (const float*)d_in[4];
    const float* Wo = (const float*)d_in[5];
    const float* bo = (const float*)d_in[6];
    float* out = (float*)d_out;

    cudaFuncSetAttribute(k_gemm_gv,   cudaFuncAttributeMaxDynamicSharedMemorySize, SMEM_G);
    cudaFuncSetAttribute(k_gemm_o,    cudaFuncAttributeMaxDynamicSharedMemorySize, SMEM_G);
    cudaFuncSetAttribute(k_scores_mma,cudaFuncAttributeMaxDynamicSharedMemorySize, SMEM_S);
    cudaFuncSetAttribute(k_attnv,     cudaFuncAttributeMaxDynamicSharedMemorySize, ATTN_SMEM);

    k_conv_x  <<<(TT * DD) / 1024, 256>>>(x);                 // #1
    k_conv_wgv<<<(2 * DD * DD) / 1024, 256>>>(Wg, Wv);        // #2

    dim3 gemm_gv(DD / 64, TT / 128, 2);
    k_gemm_gv<<<gemm_gv, 256, SMEM_G>>>(bg, bv);              // #3

    dim3 sc_grid(TT / SIT, NH);
    k_scores_mma<<<sc_grid, 256, SMEM_S>>>();                 // #4 (ncu slot)

    dim3 av_grid(TT / IT, NH);
    k_attnv<<<av_grid, 256, ATTN_SMEM>>>();                   // #5

    k_conv_wo<<<(DD * DD) / 1024, 256>>>(Wo);                 // #6

    dim3 gemm_o(DD / 64, TT / 128, 1);
    k_gemm_o<<<gemm_o, 256, SMEM_G>>>(bo, out);               // #7
}

// round 9
// speedup vs baseline: 1.8123x; 1.1972x over previous
#include <cuda_runtime.h>
#include <cuda_bf16.h>
#include <math.h>
#include <stdint.h>

#define TT   2048
#define DD   1024
#define NH   16
#define HDIM 64
#define WIN  128
#define PSTR 132
#define IT   16
#define JTA  148
#define SIT  64     // scores i-tile
#define SPAN 192    // scores j-window (64 + 128)

// ---------------- scratch (static device globals; no allocation) ----------
__device__ float v_buf[TT * DD];
__device__ float norm_buf[NH * TT];
__device__ float denom_buf[NH * TT];
__device__ float suminv_buf[NH];
__device__ float p_buf[(size_t)NH * TT * PSTR];

__device__ __nv_bfloat16 xh_buf[TT * DD], xl_buf[TT * DD];
__device__ __nv_bfloat16 gh_buf[TT * DD], gl_buf[TT * DD];
__device__ __nv_bfloat16 oh_buf[TT * DD], ol_buf[TT * DD];
__device__ __nv_bfloat16 wgh_buf[DD * DD], wgl_buf[DD * DD];
__device__ __nv_bfloat16 wvh_buf[DD * DD], wvl_buf[DD * DD];
__device__ __nv_bfloat16 woh_buf[DD * DD], wol_buf[DD * DD];

// ---------------- PTX helpers ----------------------------------------------
__device__ __forceinline__ uint32_t s2u(const void* p) {
    uint32_t a;
    asm("{ .reg .u64 t; cvta.to.shared.u64 t, %1; cvt.u32.u64 %0, t; }"
        : "=r"(a) : "l"(p));
    return a;
}
#define CP_ASYNC16(dst, src) \
    asm volatile("cp.async.cg.shared.global [%0], [%1], 16;" :: "r"(dst), "l"(src))
#define CP_COMMIT()  asm volatile("cp.async.commit_group;" ::: "memory")
#define CP_WAIT2()   asm volatile("cp.async.wait_group 2;" ::: "memory")
#define CP_WAIT1()   asm volatile("cp.async.wait_group 1;" ::: "memory")
#define CP_WAIT0()   asm volatile("cp.async.wait_group 0;" ::: "memory")

__device__ __forceinline__ void ldsm_x4(uint32_t& r0, uint32_t& r1,
                                        uint32_t& r2, uint32_t& r3, uint32_t a) {
    asm volatile("ldmatrix.sync.aligned.m8n8.x4.shared.b16 {%0,%1,%2,%3}, [%4];"
                 : "=r"(r0), "=r"(r1), "=r"(r2), "=r"(r3) : "r"(a));
}
__device__ __forceinline__ void mma16816(float* d, const uint32_t* a, const uint32_t* b) {
    asm volatile(
        "mma.sync.aligned.m16n8k16.row.col.f32.bf16.bf16.f32 "
        "{%0,%1,%2,%3}, {%4,%5,%6,%7}, {%8,%9}, {%0,%1,%2,%3};"
        : "+f"(d[0]), "+f"(d[1]), "+f"(d[2]), "+f"(d[3])
        : "r"(a[0]), "r"(a[1]), "r"(a[2]), "r"(a[3]), "r"(b[0]), "r"(b[1]));
}
__device__ __forceinline__ uint32_t sw64(uint32_t off) {
    return off ^ ((off >> 3) & 0x30u);
}
__device__ __forceinline__ uint32_t sw128(uint32_t off) {
    return off ^ ((off >> 3) & 0x70u);
}

// ---------------- fp32->bf16 hi/lo split ------------------------------------
__device__ __forceinline__ void split_store(const float* __restrict__ src,
                                            __nv_bfloat16* __restrict__ dh,
                                            __nv_bfloat16* __restrict__ dl, int i)
{
    float4 v = ((const float4*)src)[i];
    __nv_bfloat16 h0 = __float2bfloat16(v.x), h1 = __float2bfloat16(v.y),
                  h2 = __float2bfloat16(v.z), h3 = __float2bfloat16(v.w);
    __nv_bfloat16 l0 = __float2bfloat16(v.x - __bfloat162float(h0)),
                  l1 = __float2bfloat16(v.y - __bfloat162float(h1)),
                  l2 = __float2bfloat16(v.z - __bfloat162float(h2)),
                  l3 = __float2bfloat16(v.w - __bfloat162float(h3));
    __nv_bfloat162 hp0(h0, h1), hp1(h2, h3), lp0(l0, l1), lp1(l2, l3);
    uint2 uh, ul;
    uh.x = *(unsigned*)&hp0; uh.y = *(unsigned*)&hp1;
    ul.x = *(unsigned*)&lp0; ul.y = *(unsigned*)&lp1;
    ((uint2*)dh)[i] = uh;
    ((uint2*)dl)[i] = ul;
}

// one kernel converts x, Wg, Wv, Wo (block-range dispatch)
__global__ void __launch_bounds__(256)
k_conv_all(const float* __restrict__ x,  const float* __restrict__ Wg,
           const float* __restrict__ Wv, const float* __restrict__ Wo)
{
    const int b = blockIdx.x;
    if (b == 0 && threadIdx.x < NH) suminv_buf[threadIdx.x] = 0.f;
    if (b < 2048) {
        split_store(x, xh_buf, xl_buf, b * 256 + threadIdx.x);
    } else if (b < 3072) {
        split_store(Wg, wgh_buf, wgl_buf, (b - 2048) * 256 + threadIdx.x);
    } else if (b < 4096) {
        split_store(Wv, wvh_buf, wvl_buf, (b - 3072) * 256 + threadIdx.x);
    } else {
        split_store(Wo, woh_buf, wol_buf, (b - 4096) * 256 + threadIdx.x);
    }
}

// ---------------- HMMA bf16-split GEMM --------------------------------------
#define KC32   32
#define NC     (DD / KC32)
#define ATSZ   8192
#define BTSZ   4096
#define STG    (2 * ATSZ + 2 * BTSZ)
#define NSTAGE 4
#define SMEM_G (NSTAGE * STG)

__device__ __forceinline__ void load_stage(
    const uint4* __restrict__ Ah4, const uint4* __restrict__ Al4,
    const uint4* __restrict__ Bh4, const uint4* __restrict__ Bl4,
    uint32_t sb, int slot, int c, int m0, int n0, int tid)
{
    const uint32_t base = sb + slot * STG;
    const int q = tid & 3;
#pragma unroll
    for (int t = 0; t < 4; ++t) {
        const int row = (t * 64 + (tid >> 2)) & 127;
        const uint32_t dst = base + (t >> 1) * ATSZ + sw64((uint32_t)row * 64u + q * 16u);
        const uint4* src = ((t >> 1) ? Al4 : Ah4)
                         + (size_t)(m0 + row) * (DD / 8) + c * 4 + q;
        CP_ASYNC16(dst, src);
    }
#pragma unroll
    for (int t = 0; t < 2; ++t) {
        const int row = tid >> 2;
        const uint32_t dst = base + 2 * ATSZ + t * BTSZ
                           + sw64((uint32_t)row * 64u + q * 16u);
        const uint4* src = (t ? Bl4 : Bh4)
                         + (size_t)(n0 + row) * (DD / 8) + c * 4 + q;
        CP_ASYNC16(dst, src);
    }
}

__device__ __forceinline__ void gemm_core(
    const uint4* __restrict__ Ah4, const uint4* __restrict__ Al4,
    const uint4* __restrict__ Bh4, const uint4* __restrict__ Bl4,
    const float* __restrict__ bias, float* __restrict__ C, bool doNorm)
{
    extern __shared__ char smem[];
    __shared__ float ssrow[128];
    const uint32_t sb = s2u(smem);
    const int tid  = threadIdx.x;
    const int wid  = tid >> 5;
    const int lane = tid & 31;
    const int n0 = blockIdx.x * 64, m0 = blockIdx.y * 128;

    const int wm = wid >> 1;
    const int wn = wid & 1;

    const int r  = lane & 7;
    const int md = lane >> 3;
    const int rowA = wm * 32 + (md & 1) * 8 + r;
    const uint32_t bA = (md >> 1) * 16;
    const int rowB = wn * 32 + (md >> 1) * 8 + r;
    const uint32_t bB = (md & 1) * 16;

    if (doNorm && tid < 128) ssrow[tid] = 0.f;

    float acc[2][4][4];
#pragma unroll
    for (int f = 0; f < 2; ++f)
#pragma unroll
        for (int j = 0; j < 4; ++j)
#pragma unroll
            for (int e = 0; e < 4; ++e) acc[f][j][e] = 0.f;

    load_stage(Ah4, Al4, Bh4, Bl4, sb, 0, 0, m0, n0, tid); CP_COMMIT();
    load_stage(Ah4, Al4, Bh4, Bl4, sb, 1, 1, m0, n0, tid); CP_COMMIT();
    load_stage(Ah4, Al4, Bh4, Bl4, sb, 2, 2, m0, n0, tid); CP_COMMIT();

#pragma unroll 1
    for (int c = 0; c < NC; ++c) {
        const int rem = NC - 1 - c;
        if (rem >= 2) CP_WAIT2(); else if (rem == 1) CP_WAIT1(); else CP_WAIT0();
        __syncthreads();

        const uint32_t base = sb + (c & 3) * STG;
        const uint32_t stAh = base;
        const uint32_t stAl = base + ATSZ;
        const uint32_t stBh = base + 2 * ATSZ;
        const uint32_t stBl = base + 2 * ATSZ + BTSZ;

#pragma unroll
        for (int ks = 0; ks < 2; ++ks) {
            const uint32_t kb = ks * 32;
            uint32_t ah[2][4], al[2][4];
#pragma unroll
            for (int f = 0; f < 2; ++f) {
                const uint32_t off = sw64((uint32_t)(rowA + f * 16) * 64u + kb + bA);
                ldsm_x4(ah[f][0], ah[f][1], ah[f][2], ah[f][3], stAh + off);
                ldsm_x4(al[f][0], al[f][1], al[f][2], al[f][3], stAl + off);
            }
            uint32_t bh[4][2], bl[4][2];
#pragma unroll
            for (int p = 0; p < 2; ++p) {
                const uint32_t off = sw64((uint32_t)(rowB + p * 16) * 64u + kb + bB);
                ldsm_x4(bh[2*p][0], bh[2*p][1], bh[2*p+1][0], bh[2*p+1][1], stBh + off);
                ldsm_x4(bl[2*p][0], bl[2*p][1], bl[2*p+1][0], bl[2*p+1][1], stBl + off);
            }
#pragma unroll
            for (int f = 0; f < 2; ++f)
#pragma unroll
                for (int j = 0; j < 4; ++j) {
                    mma16816(acc[f][j], ah[f], bh[j]);
                    mma16816(acc[f][j], ah[f], bl[j]);
                    mma16816(acc[f][j], al[f], bh[j]);
                }
        }
        if (c + 3 < NC) {
            load_stage(Ah4, Al4, Bh4, Bl4, sb, (c + 3) & 3, c + 3, m0, n0, tid);
            CP_COMMIT();
        }
    }

    // epilogue
#pragma unroll
    for (int f = 0; f < 2; ++f) {
        const int grow = m0 + wm * 32 + f * 16 + (lane >> 2);
        float ss0 = 0.f, ss1 = 0.f;
#pragma unroll
        for (int j = 0; j < 4; ++j) {
            const int col = n0 + wn * 32 + j * 8 + (lane & 3) * 2;
            const float2 bb = *(const float2*)(bias + col);
            float2 o0 = make_float2(acc[f][j][0] + bb.x, acc[f][j][1] + bb.y);
            float2 o1 = make_float2(acc[f][j][2] + bb.x, acc[f][j][3] + bb.y);
            if (doNorm) {
                const size_t p0 = ((size_t)grow * DD + col) >> 1;
                const size_t p1 = ((size_t)(grow + 8) * DD + col) >> 1;
                __nv_bfloat16 h00 = __float2bfloat16(o0.x), h01 = __float2bfloat16(o0.y);
                __nv_bfloat16 h10 = __float2bfloat16(o1.x), h11 = __float2bfloat16(o1.y);
                __nv_bfloat16 l00 = __float2bfloat16(o0.x - __bfloat162float(h00));
                __nv_bfloat16 l01 = __float2bfloat16(o0.y - __bfloat162float(h01));
                __nv_bfloat16 l10 = __float2bfloat16(o1.x - __bfloat162float(h10));
                __nv_bfloat16 l11 = __float2bfloat16(o1.y - __bfloat162float(h11));
                ((__nv_bfloat162*)gh_buf)[p0] = __nv_bfloat162(h00, h01);
                ((__nv_bfloat162*)gl_buf)[p0] = __nv_bfloat162(l00, l01);
                ((__nv_bfloat162*)gh_buf)[p1] = __nv_bfloat162(h10, h11);
                ((__nv_bfloat162*)gl_buf)[p1] = __nv_bfloat162(l10, l11);
                ss0 = fmaf(o0.x, o0.x, fmaf(o0.y, o0.y, ss0));
                ss1 = fmaf(o1.x, o1.x, fmaf(o1.y, o1.y, ss1));
            } else {
                float* c0 = C + (size_t)grow * DD;
                *(float2*)(c0 + col) = o0;
                *(float2*)(c0 + 8 * DD + col) = o1;
            }
        }
        if (doNorm) {
            ss0 += __shfl_xor_sync(0xffffffffu, ss0, 1);
            ss0 += __shfl_xor_sync(0xffffffffu, ss0, 2);
            ss1 += __shfl_xor_sync(0xffffffffu, ss1, 1);
            ss1 += __shfl_xor_sync(0xffffffffu, ss1, 2);
            if ((lane & 3) == 0) {
                const int l0 = wm * 32 + f * 16 + (lane >> 2);
                atomicAdd(&ssrow[l0], ss0);
                atomicAdd(&ssrow[l0 + 8], ss1);
            }
        }
    }
    if (doNorm) {
        __syncthreads();
        if (tid < 128) {
            const int h = n0 >> 6;
            norm_buf[h * TT + m0 + tid] = sqrtf(ssrow[tid]);
        }
    }
}

__global__ void __launch_bounds__(256, 2)
k_gemm_gv(const float* __restrict__ bg, const float* __restrict__ bv)
{
    if (blockIdx.z == 0)
        gemm_core((const uint4*)xh_buf, (const uint4*)xl_buf,
                  (const uint4*)wgh_buf, (const uint4*)wgl_buf, bg, nullptr, true);
    else
        gemm_core((const uint4*)xh_buf, (const uint4*)xl_buf,
                  (const uint4*)wvh_buf, (const uint4*)wvl_buf, bv, v_buf, false);
}

__global__ void __launch_bounds__(256, 2)
k_gemm_o(const float* __restrict__ bo, float* __restrict__ out)
{
    gemm_core((const uint4*)oh_buf, (const uint4*)ol_buf,
              (const uint4*)woh_buf, (const uint4*)wol_buf, bo, out, false);
}

// ---------------- MMA banded scores ------------------------------------------
#define WTSZ   (SPAN * 128)
#define SMEM_S (2 * WTSZ)

__global__ void __launch_bounds__(256)
k_scores_mma()
{
    extern __shared__ char smem[];
    __shared__ float nwin[SPAN];
    __shared__ float rowsum[SIT];
    __shared__ float sinv[SIT];

    const uint32_t sbH = s2u(smem);
    const uint32_t sbL = sbH + WTSZ;
    const int tid  = threadIdx.x;
    const int wid  = tid >> 5;
    const int lane = tid & 31;
    const int i0 = blockIdx.x * SIT;
    const int h  = blockIdx.y;

    const int jstart0 = (i0 > WIN) ? (i0 - WIN) : 0;
    const int qbase   = i0 - jstart0;

    const uint4* gh4 = (const uint4*)gh_buf;
    const uint4* gl4 = (const uint4*)gl_buf;
#pragma unroll
    for (int t = 0; t < 6; ++t) {
        const int idx = t * 256 + tid;
        const int row = idx >> 3;
        const int q   = idx & 7;
        const uint32_t d = sw128((uint32_t)row * 128u + q * 16u);
        const size_t g = (size_t)(jstart0 + row) * (DD / 8) + h * 8 + q;
        CP_ASYNC16(sbH + d, gh4 + g);
        CP_ASYNC16(sbL + d, gl4 + g);
    }
    CP_COMMIT();
    if (tid < SPAN) nwin[tid] = norm_buf[h * TT + jstart0 + tid];
    if (tid < SIT) rowsum[tid] = 0.f;
    CP_WAIT0();
    __syncthreads();

    const int wm = wid >> 1;
    const int wn = wid & 1;

    const int r  = lane & 7;
    const int md = lane >> 3;
    const int arow  = qbase + wm * 16 + (md & 1) * 8 + r;
    const uint32_t abyte = (md >> 1) * 16;
    const int brow0 = wn * 96 + (md >> 1) * 8 + r;
    const uint32_t bbyte = (md & 1) * 16;

    float acc[12][4];
#pragma unroll
    for (int nt = 0; nt < 12; ++nt)
#pragma unroll
        for (int e = 0; e < 4; ++e) acc[nt][e] = 0.f;

#pragma unroll
    for (int ks = 0; ks < 4; ++ks) {
        const uint32_t kb = ks * 32;
        uint32_t ah[4], al[4];
        const uint32_t aoff = sw128((uint32_t)arow * 128u + kb + abyte);
        ldsm_x4(ah[0], ah[1], ah[2], ah[3], sbH + aoff);
        ldsm_x4(al[0], al[1], al[2], al[3], sbL + aoff);
#pragma unroll
        for (int bt = 0; bt < 6; ++bt) {
            uint32_t bh[2][2], bl[2][2];
            const uint32_t boff = sw128((uint32_t)(brow0 + bt * 16) * 128u + kb + bbyte);
            ldsm_x4(bh[0][0], bh[0][1], bh[1][0], bh[1][1], sbH + boff);
            ldsm_x4(bl[0][0], bl[0][1], bl[1][0], bl[1][1], sbL + boff);
#pragma unroll
            for (int p = 0; p < 2; ++p) {
                mma16816(acc[2*bt + p], ah, bh[p]);
                mma16816(acc[2*bt + p], ah, bl[p]);
                mma16816(acc[2*bt + p], al, bh[p]);
            }
        }
    }

    const int quad = lane >> 2;
    const int cp2  = (lane & 3) * 2;
    const int gi0 = i0 + wm * 16 + quad;
    const int gi1 = gi0 + 8;
    const float ni0 = nwin[qbase + wm * 16 + quad];
    const float ni1 = nwin[qbase + wm * 16 + quad + 8];
    const int off0 = (gi0 > WIN) ? (gi0 - WIN) : 0;
    const int off1 = (gi1 > WIN) ? (gi1 - WIN) : 0;
    float* pr0 = p_buf + (size_t)(h * TT + gi0) * PSTR;
    float* pr1 = p_buf + (size_t)(h * TT + gi1) * PSTR;
    float ps0 = 0.f, ps1 = 0.f;

#pragma unroll
    for (int nt = 0; nt < 12; ++nt) {
        const int jl = wn * 96 + nt * 8 + cp2;
        const int jg = jstart0 + jl;
        const float nj0 = nwin[jl];
        const float nj1 = nwin[jl + 1];
#pragma unroll
        for (int e = 0; e < 4; ++e) {
            const int  jj = jg + (e & 1);
            const float nj = (e & 1) ? nj1 : nj0;
            const int  gi  = (e >> 1) ? gi1 : gi0;
            const float ni = (e >> 1) ? ni1 : ni0;
            const int  off = (e >> 1) ? off1 : off0;
            if (jj <= gi && jj >= off) {
                float c = acc[nt][e] / (ni * nj + 1e-8f);
                if (c != c) c = 0.f;
                float p = (c + 1.f) * 0.5f;
                ((e >> 1) ? pr1 : pr0)[jj - off] = p;
                if (e >> 1) ps1 += p; else ps0 += p;
            }
        }
    }

    ps0 += __shfl_xor_sync(0xffffffffu, ps0, 1);
    ps0 += __shfl_xor_sync(0xffffffffu, ps0, 2);
    ps1 += __shfl_xor_sync(0xffffffffu, ps1, 1);
    ps1 += __shfl_xor_sync(0xffffffffu, ps1, 2);
    if ((lane & 3) == 0) {
        atomicAdd(&rowsum[wm * 16 + quad], ps0);
        atomicAdd(&rowsum[wm * 16 + quad + 8], ps1);
    }
    __syncthreads();

    // per-row denom; block-reduce 1/dn; ONE global atomic per block
    if (tid < SIT) {
        const int i   = i0 + tid;
        const int cnt = i - ((i > WIN) ? (i - WIN) : 0) + 1;
        float gm = (rowsum[tid] + 0.5f * (float)(TT - cnt)) * (1.f / (float)TT);
        float dn = gm + 0.5f;
        denom_buf[h * TT + i] = dn;
        sinv[tid] = 1.f / dn;
    }
    __syncthreads();
    if (tid < 32) {
        float s = sinv[tid] + sinv[tid + 32];
#pragma unroll
        for (int o = 16; o > 0; o >>= 1) s += __shfl_xor_sync(0xffffffffu, s, o);
        if (tid == 0) atomicAdd(&suminv_buf[h], s);
    }
}

// ---------------- softmax + attn@v (16 rows / block), emits bf16 hi/lo -----
#define SATT_STRIDE 20
#define ATTN_SMEM   (JTA * HDIM * 4 + JTA * SATT_STRIDE * 4 + 4 * IT * HDIM * 4 + 64)

__global__ void __launch_bounds__(256)
k_attnv()
{
    extern __shared__ char dynsm[];
    float (*vw)[HDIM]       = (float(*)[HDIM])dynsm;
    float (*sattn)[SATT_STRIDE] =
        (float(*)[SATT_STRIDE])(dynsm + JTA * HDIM * 4);
    float (*red)[IT][HDIM]  =
        (float(*)[IT][HDIM])(dynsm + JTA * HDIM * 4 + JTA * SATT_STRIDE * 4);
    float* invs = (float*)(dynsm + JTA * HDIM * 4 + JTA * SATT_STRIDE * 4
                           + 4 * IT * HDIM * 4);

    const int i0  = blockIdx.x * IT;
    const int h   = blockIdx.y;
    const int tid = threadIdx.x;
    const int wid = tid >> 5;
    const int lane = tid & 31;

    const int jstart0 = (i0 > WIN) ? (i0 - WIN) : 0;
    const int span    = (i0 + IT - 1) - jstart0 + 1;

    const float4* v4 = (const float4*)v_buf;
    for (int idx = tid; idx < span * 16; idx += 256) {
        int jj = idx >> 4;
        int q  = idx & 15;
        ((float4*)&vw[jj][0])[q] = v4[(size_t)(jstart0 + jj) * (DD / 4) + h * (HDIM / 4) + q];
    }
    __syncthreads();

#pragma unroll
    for (int rr = 0; rr < 2; ++rr) {
        const int w = wid + rr * 8;
        const int i = i0 + w;
        const size_t row = (size_t)h * TT + i;
        const float fit  = 1.f / (denom_buf[row] * suminv_buf[h]);
        const int off = ((i > WIN) ? (i - WIN) : 0) - jstart0;
        const int wi  = i - jstart0;

        float m = -1e30f;
        for (int q = lane; q < JTA; q += 32) {
            bool in = (q >= off) && (q <= wi);
            float s = in ? fit * p_buf[row * PSTR + (q - off)] : -1e30f;
            sattn[q][w] = s;
            m = fmaxf(m, s);
        }
#pragma unroll
        for (int o = 16; o > 0; o >>= 1) m = fmaxf(m, __shfl_xor_sync(0xffffffffu, m, o));

        float ss = 0.f;
        for (int q = lane; q < JTA; q += 32) {
            float e = expf(sattn[q][w] - m);
            sattn[q][w] = e;
            ss += e;
        }
#pragma unroll
        for (int o = 16; o > 0; o >>= 1) ss += __shfl_xor_sync(0xffffffffu, ss, o);
        if (lane == 0) invs[w] = 1.f / ss;
    }
    __syncthreads();

    {
        const int d  = tid & 63;
        const int qq = tid >> 6;
        float acc[IT];
#pragma unroll
        for (int w = 0; w < IT; ++w) acc[w] = 0.f;

        for (int jj = qq; jj < span; jj += 4) {
            const float vv = vw[jj][d];
            const float4 s0 = *(const float4*)&sattn[jj][0];
            const float4 s1 = *(const float4*)&sattn[jj][4];
            const float4 s2 = *(const float4*)&sattn[jj][8];
            const float4 s3 = *(const float4*)&sattn[jj][12];
            acc[0]  = fmaf(s0.x, vv, acc[0]);  acc[1]  = fmaf(s0.y, vv, acc[1]);
            acc[2]  = fmaf(s0.z, vv, acc[2]);  acc[3]  = fmaf(s0.w, vv, acc[3]);
            acc[4]  = fmaf(s1.x, vv, acc[4]);  acc[5]  = fmaf(s1.y, vv, acc[5]);
            acc[6]  = fmaf(s1.z, vv, acc[6]);  acc[7]  = fmaf(s1.w, vv, acc[7]);
            acc[8]  = fmaf(s2.x, vv, acc[8]);  acc[9]  = fmaf(s2.y, vv, acc[9]);
            acc[10] = fmaf(s2.z, vv, acc[10]); acc[11] = fmaf(s2.w, vv, acc[11]);
            acc[12] = fmaf(s3.x, vv, acc[12]); acc[13] = fmaf(s3.y, vv, acc[13]);
            acc[14] = fmaf(s3.z, vv, acc[14]); acc[15] = fmaf(s3.w, vv, acc[15]);
        }
#pragma unroll
        for (int w = 0; w < IT; ++w) red[qq][w][d] = acc[w];
        __syncthreads();

        if (qq == 0) {
#pragma unroll
            for (int w = 0; w < IT; ++w) {
                float s = (red[0][w][d] + red[1][w][d]) + (red[2][w][d] + red[3][w][d]);
                float val = s * invs[w];
                const size_t idx = (size_t)(i0 + w) * DD + h * HDIM + d;
                __nv_bfloat16 hv = __float2bfloat16(val);
                __nv_bfloat16 lv = __float2bfloat16(val - __bfloat162float(hv));
                oh_buf[idx] = hv;
                ol_buf[idx] = lv;
            }
        }
    }
}

// ---------------- launch ---------------------------------------------------
extern "C" void kernel_launch(void* const* d_in, const int* in_sizes, int n_in,
                              void* d_out, int out_size)
{
    const float* x  = (const float*)d_in[0];
    const float* Wg = (const float*)d_in[1];
    const float* bg = (const float*)d_in[2];
    const float* Wv = (const float*)d_in[3];
    const float* bv = (const float*)d_in[4];
    const float* Wo = (const float*)d_in[5];
    const float* bo = (const float*)d_in[6];
    float* out = (float*)d_out;

    cudaFuncSetAttribute(k_gemm_gv,   cudaFuncAttributeMaxDynamicSharedMemorySize, SMEM_G);
    cudaFuncSetAttribute(k_gemm_o,    cudaFuncAttributeMaxDynamicSharedMemorySize, SMEM_G);
    cudaFuncSetAttribute(k_scores_mma,cudaFuncAttributeMaxDynamicSharedMemorySize, SMEM_S);
    cudaFuncSetAttribute(k_attnv,     cudaFuncAttributeMaxDynamicSharedMemorySize, ATTN_SMEM);

    k_conv_all<<<5120, 256>>>(x, Wg, Wv, Wo);                 // #1

    dim3 gemm_gv(DD / 64, TT / 128, 2);
    k_gemm_gv<<<gemm_gv, 256, SMEM_G>>>(bg, bv);              // #2

    dim3 sc_grid(TT / SIT, NH);
    k_scores_mma<<<sc_grid, 256, SMEM_S>>>();                 // #3

    dim3 av_grid(TT / IT, NH);
    k_attnv<<<av_grid, 256, ATTN_SMEM>>>();                   // #4 (ncu slot)

    dim3 gemm_o(DD / 64, TT / 128, 1);
    k_gemm_o<<<gemm_o, 256, SMEM_G>>>(bo, out);               // #5
}